// round 16
// baseline (speedup 1.0000x reference)
#include <cuda_runtime.h>
#include <math.h>
#include <float.h>

// RepulsionLoss: B=8, N=4096, KNN=4, H=0.03
// 2D grid pruning (64x64 cells, width 0.15): neighbors outside the 3x3 cell
// window have weight <= e^-25, negligible. TWO kernels only:
//   K1: direct cell-slot bucketing (atomicAdd rank; slot order free).
//   K2: per-query 3x3-window KNN (2 splits) + loss + fused fixed-order reduce.
// Selection = exact min/max network over the 5 smallest -> invariant to slot
// order; loss stored at the query's ORIGINAL index and reduced in fixed order
// -> deterministic output. Self = strict min -> slot 0, dropped (matches
// reference top_k(KNN+1)-drop-first).

#define B_SZ     8
#define N_SZ     4096
#define NPTS     (B_SZ * N_SZ)
#define ND       64
#define NCELL    (ND * ND)
#define CAP      48                           // max pts/cell (center mean ~15)
#define WID      0.15f
#define X0       (-4.8f)
#define INVW     (1.0f / WID)
#define H2       (0.03f * 0.03f)
#define FULL     0xffffffffu

#define STHREADS 256
#define SGRID    ((NPTS * 2) / STHREADS)     // 256 blocks, 2 splits/query

__device__ float4 g_slots[(size_t)B_SZ * NCELL * CAP];  // ~25 MB, cell-major
__device__ int    g_cnt[B_SZ * NCELL];       // zero-init; reset by K2 tail
__device__ float4 g_aug[NPTS];               // (x,y,z,|p|^2) original order
__device__ float  g_loss[NPTS];
__device__ int    g_done;                    // zero-init; self-resetting

#define CE(x, y) { float t_ = fminf((x), (y)); (y) = fmaxf((x), (y)); (x) = t_; }

__device__ __forceinline__ void ins5(float& d0, float& d1, float& d2,
                                     float& d3, float& d4, float v) {
    d4 = fminf(d4, v);
    CE(d3, d4) CE(d2, d3) CE(d1, d2) CE(d0, d1)
}

// K1: bucket every point into its cell's slot array (32 blocks, full chip).
__global__ __launch_bounds__(1024)
void build_kernel(const float* __restrict__ pc) {
    const int i  = blockIdx.x * 1024 + threadIdx.x;     // 0..NPTS-1
    const int bt = i >> 12;
    const float* s = pc + (size_t)i * 3;
    float x = s[0], y = s[1], z = s[2];
    int bx = min(ND - 1, max(0, (int)((x - X0) * INVW)));
    int by = min(ND - 1, max(0, (int)((y - X0) * INVW)));
    int cell = bt * NCELL + bx * ND + by;
    float4 p = make_float4(x, y, z, fmaf(x, x, fmaf(y, y, z * z)));
    g_aug[i] = p;
    int r = atomicAdd(&g_cnt[cell], 1);
    if (r < CAP) g_slots[(size_t)cell * CAP + r] = p;   // overflow-safe
}

// K2: 3x3-window KNN (2 splits/query) + loss + fused deterministic reduce.
__global__ __launch_bounds__(STHREADS)
void repulsion_grid_kernel(float* __restrict__ out) {
    __shared__ float wsum[STHREADS / 32];
    __shared__ int   is_last;

    const int g     = blockIdx.x * STHREADS + threadIdx.x;
    const int s     = g >> 1;                  // ORIGINAL query index
    const int split = g & 1;
    const int bt    = s >> 12;
    const int tid   = threadIdx.x;

    float4 q = g_aug[s];
    const float m2x = -2.0f * q.x, m2y = -2.0f * q.y, m2z = -2.0f * q.z;
    const float qsq = q.w;

    int bx = min(ND - 1, max(0, (int)((q.x - X0) * INVW)));
    int by = min(ND - 1, max(0, (int)((q.y - X0) * INVW)));
    const int cxlo = max(bx - 1, 0), cxhi = min(bx + 1, ND - 1);
    const int cylo = max(by - 1, 0), cyhi = min(by + 1, ND - 1);
    const int cb   = bt * NCELL;

    float d0 = FLT_MAX, d1 = FLT_MAX, d2 = FLT_MAX, d3 = FLT_MAX, d4 = FLT_MAX;

    for (int cx = cxlo; cx <= cxhi; ++cx) {
        for (int cy = cylo; cy <= cyhi; ++cy) {
            const int c = cb + cx * ND + cy;
            int n = min(g_cnt[c], CAP);
            const float4* __restrict__ sl = g_slots + (size_t)c * CAP;
            const int mid = n >> 1;
            const int lo = split ? mid : 0;
            const int hi = split ? n : mid;
            for (int i = lo; i < hi; i += 4) {
                float4 p0 = sl[i];
                float4 p1 = sl[min(i + 1, CAP - 1)];
                float4 p2 = sl[min(i + 2, CAP - 1)];
                float4 p3 = sl[min(i + 3, CAP - 1)];
                float va = fmaf(p0.x, m2x, fmaf(p0.y, m2y, fmaf(p0.z, m2z, p0.w)));
                float vb = fmaf(p1.x, m2x, fmaf(p1.y, m2y, fmaf(p1.z, m2z, p1.w)));
                float vc = fmaf(p2.x, m2x, fmaf(p2.y, m2y, fmaf(p2.z, m2z, p2.w)));
                float vd = fmaf(p3.x, m2x, fmaf(p3.y, m2y, fmaf(p3.z, m2z, p3.w)));
                vb = (i + 1 < hi) ? vb : FLT_MAX;   // tail guards
                vc = (i + 2 < hi) ? vc : FLT_MAX;
                vd = (i + 3 < hi) ? vd : FLT_MAX;
                CE(va, vb) CE(vc, vd) CE(va, vc) CE(vb, vd) CE(vb, vc)
                d1 = fminf(d1, vd); d2 = fminf(d2, vc);
                d3 = fminf(d3, vb); d4 = fminf(d4, va);
                CE(d0, d4) CE(d1, d3) CE(d2, d4) CE(d1, d2) CE(d3, d4)
            }
        }
    }

    // Merge the two splits of this query (lane pairs 2k, 2k+1).
    {
        float o0 = __shfl_xor_sync(FULL, d0, 1);
        float o1 = __shfl_xor_sync(FULL, d1, 1);
        float o2 = __shfl_xor_sync(FULL, d2, 1);
        float o3 = __shfl_xor_sync(FULL, d3, 1);
        float o4 = __shfl_xor_sync(FULL, d4, 1);
        ins5(d0, d1, d2, d3, d4, o0);
        ins5(d0, d1, d2, d3, d4, o1);
        ins5(d0, d1, d2, d3, d4, o2);
        ins5(d0, d1, d2, d3, d4, o3);
        ins5(d0, d1, d2, d3, d4, o4);
    }

    if (split == 0) {
        const float inv = -1.0f / H2;
        float loss = 0.0f, t;
        t = fmaxf(d1 + qsq, 0.0f); loss -= t * expf(t * inv);
        t = fmaxf(d2 + qsq, 0.0f); loss -= t * expf(t * inv);
        t = fmaxf(d3 + qsq, 0.0f); loss -= t * expf(t * inv);
        t = fmaxf(d4 + qsq, 0.0f); loss -= t * expf(t * inv);
        g_loss[s] = loss;                      // original-index scatter
    }

    __threadfence();                           // publish g_loss writes
    __syncthreads();
    if (tid == 0) {
        int n = atomicAdd(&g_done, 1);
        is_last = (n == SGRID - 1);
    }
    __syncthreads();

    // Last block: fixed-order reduction + counter resets for next replay.
    if (is_last) {
        __threadfence();
        const float4* lv = (const float4*)g_loss;
        float acc = 0.0f;
        #pragma unroll
        for (int j = 0; j < NPTS / 4 / STHREADS; ++j) {   // 32 float4s/thread
            float4 v = lv[j * STHREADS + tid];
            acc += (v.x + v.y) + (v.z + v.w);
        }
        #pragma unroll
        for (int o = 16; o > 0; o >>= 1)
            acc += __shfl_down_sync(FULL, acc, o);
        if ((tid & 31) == 0) wsum[tid >> 5] = acc;

        // Reset cell counters for the next graph replay.
        #pragma unroll
        for (int j = tid; j < B_SZ * NCELL; j += STHREADS) g_cnt[j] = 0;

        __syncthreads();
        if (tid == 0) {
            float t = 0.0f;
            #pragma unroll
            for (int w = 0; w < STHREADS / 32; ++w) t += wsum[w];
            out[0] = t;
            g_done = 0;
        }
    }
}

extern "C" void kernel_launch(void* const* d_in, const int* in_sizes, int n_in,
                              void* d_out, int out_size) {
    const float* pc = (const float*)d_in[0];
    build_kernel<<<NPTS / 1024, 1024>>>(pc);
    repulsion_grid_kernel<<<SGRID, STHREADS>>>((float*)d_out);
}

// round 17
// speedup vs baseline: 1.1792x; 1.1792x over previous
#include <cuda_runtime.h>
#include <math.h>
#include <float.h>

// RepulsionLoss: B=8, N=4096, KNN=4, H=0.03
// 2D grid pruning (64x64 cells, width 0.15): neighbors outside the 3x3 cell
// window have weight <= e^-25, negligible. Build: 3 wide kernels (prep ->
// scan -> scatter; unordered counting sort, atomic ranks). Search: sorted-
// order queries (warp locality), 3 contiguous ranges, 2 splits/query, exact
// min/max top-5 network (order-invariant values). Reduction: per-query loss
// quantized to int64 (scale 2^44) -> integer sums are order-independent ->
// bit-deterministic output with a single atomicAdd per block.
// Self = strict min -> slot 0, dropped (ref: top_k(KNN+1)-drop-first).

#define B_SZ     8
#define N_SZ     4096
#define NPTS     (B_SZ * N_SZ)
#define ND       64
#define NCELL    (ND * ND)
#define WID      0.15f
#define X0       (-4.8f)
#define INVW     (1.0f / WID)
#define H2       (0.03f * 0.03f)
#define FULL     0xffffffffu
#define QSCALE   0x1p44f
#define IQSCALE  0x1p-44

#define STHREADS 256
#define SGRID    ((NPTS * 2) / STHREADS)     // 256 blocks, 2 splits/query

__device__ int                g_cell[NPTS];
__device__ int                g_rank[NPTS];
__device__ int                g_cnt[B_SZ * NCELL];   // zero-init; K2 resets
__device__ float4             g_sorted[NPTS + 4];    // +pad (.bss zeros)
__device__ int                g_scell[NPTS];
__device__ int                g_cst[B_SZ * (NCELL + 1)];
__device__ unsigned long long g_isum;                // zero-init; self-reset
__device__ int                g_done;                // zero-init; self-reset

#define CE(x, y) { float t_ = fminf((x), (y)); (y) = fmaxf((x), (y)); (x) = t_; }

__device__ __forceinline__ void ins5(float& d0, float& d1, float& d2,
                                     float& d3, float& d4, float v) {
    d4 = fminf(d4, v);
    CE(d3, d4) CE(d2, d3) CE(d1, d2) CE(d0, d1)
}

// K1: cells + atomic ranks (32 blocks, full chip).
__global__ __launch_bounds__(1024)
void prep_kernel(const float* __restrict__ pc) {
    const int i  = blockIdx.x * 1024 + threadIdx.x;     // 0..NPTS-1
    const int bt = i >> 12;
    const float* s = pc + (size_t)i * 3;
    int bx = min(ND - 1, max(0, (int)((s[0] - X0) * INVW)));
    int by = min(ND - 1, max(0, (int)((s[1] - X0) * INVW)));
    int cell = bx * ND + by;
    g_cell[i] = cell;
    g_rank[i] = atomicAdd(&g_cnt[bt * NCELL + cell], 1);
}

// K2: per-batch exclusive scan of 4096 bins -> g_cst; resets g_cnt.
__global__ __launch_bounds__(1024)
void scan_kernel() {
    __shared__ int wtot[32];
    __shared__ int wpre[32];
    const int tid  = threadIdx.x;
    const int bt   = blockIdx.x;
    const int warp = tid >> 5;
    const int lane = tid & 31;

    int* cnt = g_cnt + bt * NCELL;
    int  c0 = cnt[tid * 4 + 0], c1 = cnt[tid * 4 + 1];
    int  c2 = cnt[tid * 4 + 2], c3 = cnt[tid * 4 + 3];
    cnt[tid * 4 + 0] = 0; cnt[tid * 4 + 1] = 0;          // reset for replay
    cnt[tid * 4 + 2] = 0; cnt[tid * 4 + 3] = 0;

    int tsum = c0 + c1 + c2 + c3;
    int incl = tsum;
    #pragma unroll
    for (int o = 1; o < 32; o <<= 1) {
        int n = __shfl_up_sync(FULL, incl, o);
        if (lane >= o) incl += n;
    }
    if (lane == 31) wtot[warp] = incl;
    __syncthreads();
    if (warp == 0) {
        int v = wtot[lane], si = v;
        #pragma unroll
        for (int o = 1; o < 32; o <<= 1) {
            int n = __shfl_up_sync(FULL, si, o);
            if (lane >= o) si += n;
        }
        wpre[lane] = si - v;
    }
    __syncthreads();

    int base = wpre[warp] + (incl - tsum);
    int* cst = g_cst + bt * (NCELL + 1);
    cst[tid * 4 + 0] = base;
    cst[tid * 4 + 1] = base + c0;
    cst[tid * 4 + 2] = base + c0 + c1;
    cst[tid * 4 + 3] = base + c0 + c1 + c2;
    if (tid == 0) cst[NCELL] = N_SZ;
}

// K3: scatter points (recomputed from pc) into cell order.
__global__ __launch_bounds__(1024)
void scatter_kernel(const float* __restrict__ pc) {
    const int i  = blockIdx.x * 1024 + threadIdx.x;
    const int bt = i >> 12;
    const float* s = pc + (size_t)i * 3;
    float x = s[0], y = s[1], z = s[2];
    int cell = g_cell[i];
    int pos  = bt * N_SZ + g_cst[bt * (NCELL + 1) + cell] + g_rank[i];
    g_sorted[pos] = make_float4(x, y, z, fmaf(x, x, fmaf(y, y, z * z)));
    g_scell[pos]  = cell;
}

// K4: 3x3-window KNN (2 splits/query) + int64-quantized reduction.
__global__ __launch_bounds__(STHREADS)
void repulsion_grid_kernel(float* __restrict__ out) {
    __shared__ long long lsum[STHREADS / 32];
    __shared__ int       is_last;

    const int g     = blockIdx.x * STHREADS + threadIdx.x;
    const int s     = g >> 1;                  // sorted query position
    const int split = g & 1;
    const int bt    = s >> 12;
    const int tid   = threadIdx.x;

    float4 q = g_sorted[s];
    const float m2x = -2.0f * q.x, m2y = -2.0f * q.y, m2z = -2.0f * q.z;
    const float qsq = q.w;

    const int  cell = g_scell[s];
    const int  bx = cell >> 6, by = cell & (ND - 1);
    const int* cst = g_cst + bt * (NCELL + 1);
    const int  rlo  = max(by - 1, 0);
    const int  rhi  = min(by + 2, ND);
    const int  cxlo = max(bx - 1, 0);
    const int  cxhi = min(bx + 1, ND - 1);
    const int  bbase = bt << 12;

    float d0 = FLT_MAX, d1 = FLT_MAX, d2 = FLT_MAX, d3 = FLT_MAX, d4 = FLT_MAX;

    for (int cx = cxlo; cx <= cxhi; ++cx) {
        const int clo = cst[cx * ND + rlo] + bbase;
        const int chi = cst[cx * ND + rhi] + bbase;
        const int cmid = (clo + chi) >> 1;
        const int lo = split ? cmid : clo;
        const int hi = split ? chi  : cmid;
        for (int i = lo; i < hi; i += 4) {
            float4 p0 = g_sorted[i];
            float4 p1 = g_sorted[i + 1];
            float4 p2 = g_sorted[i + 2];
            float4 p3 = g_sorted[i + 3];
            float va = fmaf(p0.x, m2x, fmaf(p0.y, m2y, fmaf(p0.z, m2z, p0.w)));
            float vb = fmaf(p1.x, m2x, fmaf(p1.y, m2y, fmaf(p1.z, m2z, p1.w)));
            float vc = fmaf(p2.x, m2x, fmaf(p2.y, m2y, fmaf(p2.z, m2z, p2.w)));
            float vd = fmaf(p3.x, m2x, fmaf(p3.y, m2y, fmaf(p3.z, m2z, p3.w)));
            vb = (i + 1 < hi) ? vb : FLT_MAX;   // tail guards
            vc = (i + 2 < hi) ? vc : FLT_MAX;
            vd = (i + 3 < hi) ? vd : FLT_MAX;
            CE(va, vb) CE(vc, vd) CE(va, vc) CE(vb, vd) CE(vb, vc)
            d1 = fminf(d1, vd); d2 = fminf(d2, vc);
            d3 = fminf(d3, vb); d4 = fminf(d4, va);
            CE(d0, d4) CE(d1, d3) CE(d2, d4) CE(d1, d2) CE(d3, d4)
        }
    }

    // Merge the two splits of this query (lane pairs 2k, 2k+1).
    {
        float o0 = __shfl_xor_sync(FULL, d0, 1);
        float o1 = __shfl_xor_sync(FULL, d1, 1);
        float o2 = __shfl_xor_sync(FULL, d2, 1);
        float o3 = __shfl_xor_sync(FULL, d3, 1);
        float o4 = __shfl_xor_sync(FULL, d4, 1);
        ins5(d0, d1, d2, d3, d4, o0);
        ins5(d0, d1, d2, d3, d4, o1);
        ins5(d0, d1, d2, d3, d4, o2);
        ins5(d0, d1, d2, d3, d4, o3);
        ins5(d0, d1, d2, d3, d4, o4);
    }

    // Quantize the (order-invariant) per-query loss to int64.
    long long ll = 0;
    if (split == 0) {
        const float inv = -1.0f / H2;
        float loss = 0.0f, t;
        t = fmaxf(d1 + qsq, 0.0f); loss -= t * expf(t * inv);
        t = fmaxf(d2 + qsq, 0.0f); loss -= t * expf(t * inv);
        t = fmaxf(d3 + qsq, 0.0f); loss -= t * expf(t * inv);
        t = fmaxf(d4 + qsq, 0.0f); loss -= t * expf(t * inv);
        ll = __float2ll_rn(loss * QSCALE);
    }

    // Integer reduction: order-independent -> bit-deterministic.
    #pragma unroll
    for (int o = 16; o > 0; o >>= 1)
        ll += __shfl_down_sync(FULL, ll, o);
    if ((tid & 31) == 0) lsum[tid >> 5] = ll;
    __syncthreads();

    if (tid == 0) {
        long long bsum = 0;
        #pragma unroll
        for (int w = 0; w < STHREADS / 32; ++w) bsum += lsum[w];
        atomicAdd(&g_isum, (unsigned long long)bsum);
        __threadfence();
        int n = atomicAdd(&g_done, 1);
        is_last = (n == SGRID - 1);
    }
    __syncthreads();

    if (is_last && tid == 0) {
        __threadfence();
        long long total = (long long)g_isum;
        out[0] = (float)((double)total * IQSCALE);
        g_isum = 0;                            // reset for next graph replay
        g_done = 0;
    }
}

extern "C" void kernel_launch(void* const* d_in, const int* in_sizes, int n_in,
                              void* d_out, int out_size) {
    const float* pc = (const float*)d_in[0];
    prep_kernel<<<NPTS / 1024, 1024>>>(pc);
    scan_kernel<<<B_SZ, 1024>>>();
    scatter_kernel<<<NPTS / 1024, 1024>>>(pc);
    repulsion_grid_kernel<<<SGRID, STHREADS>>>((float*)d_out);
}